// round 1
// baseline (speedup 1.0000x reference)
#include <cuda_runtime.h>
#include <math.h>

static constexpr int Bz  = 4096;
static constexpr int Ls  = 10;
static constexpr int IND = 8;
static constexpr int Hd  = 512;
static constexpr int Gd  = 1536;   // 3*Hd

// ---------------- scratch (single __device__ array, offsets in floats) ----------------
static constexpr size_t OFF_XG_ENC  = 0;                                   // Ls*Bz*Gd
static constexpr size_t OFF_ENC_OUT = OFF_XG_ENC  + (size_t)Ls*Bz*Gd;      // Ls*Bz*Hd
static constexpr size_t OFF_ENC_W3  = OFF_ENC_OUT + (size_t)Ls*Bz*Hd;      // Ls*Bz*Hd
static constexpr size_t OFF_HG      = OFF_ENC_W3  + (size_t)Ls*Bz*Hd;      // Bz*Gd
static constexpr size_t OFF_XG_DEC  = OFF_HG      + (size_t)Bz*Gd;         // Bz*Gd
static constexpr size_t OFF_H       = OFF_XG_DEC  + (size_t)Bz*Gd;         // Bz*Hd
static constexpr size_t OFF_A       = OFF_H       + (size_t)Bz*Hd;         // Bz*Hd
static constexpr size_t OFF_CW      = OFF_A       + (size_t)Bz*Hd;         // Gd*IND
static constexpr size_t OFF_CB      = OFF_CW      + (size_t)Gd*IND;        // Gd
static constexpr size_t SCRATCH_TOTAL = OFF_CB + Gd;

__device__ float g_scratch[SCRATCH_TOTAL];

// ---------------- math helpers (fp32-accurate enough: few-ulp) ----------------
__device__ __forceinline__ float sigm_f(float x) {
    return 1.0f / (1.0f + __expf(-x));
}
__device__ __forceinline__ float tanh_f(float x) {
    float ax = fabsf(x);
    float t  = __expf(-2.0f * ax);
    float r  = __fdividef(1.0f - t, 1.0f + t);
    return copysignf(r, x);
}

// ---------------- combine: cw = enc_wih @ emb_w (1536x8), cb = enc_wih@emb_b + enc_bih ----------------
__global__ void k_combine(const float* __restrict__ enc_wih, const float* __restrict__ emb_w,
                          const float* __restrict__ emb_b,  const float* __restrict__ enc_bih,
                          float* __restrict__ cw, float* __restrict__ cb)
{
    int g   = blockIdx.x;        // 0..Gd-1
    int tid = threadIdx.x;       // 128 threads
    float p[IND + 1];
#pragma unroll
    for (int i = 0; i <= IND; i++) p[i] = 0.0f;
    const float* wr = enc_wih + (size_t)g * Hd;
    for (int k = tid; k < Hd; k += 128) {
        float wv = wr[k];
#pragma unroll
        for (int i = 0; i < IND; i++) p[i] += wv * emb_w[(size_t)k * IND + i];
        p[IND] += wv * emb_b[k];
    }
#pragma unroll
    for (int i = 0; i <= IND; i++)
        for (int o = 16; o; o >>= 1) p[i] += __shfl_xor_sync(0xffffffffu, p[i], o);
    __shared__ float red[IND + 1][4];
    int wid = tid >> 5, lane = tid & 31;
    if (!lane) {
#pragma unroll
        for (int i = 0; i <= IND; i++) red[i][wid] = p[i];
    }
    __syncthreads();
    if (tid <= IND) {
        float s = red[tid][0] + red[tid][1] + red[tid][2] + red[tid][3];
        if (tid < IND) cw[(size_t)g * IND + tid] = s;
        else           cb[g] = s + enc_bih[g];
    }
}

// ---------------- embed: xg[(l*Bz+b)*Gd + g] = items[b,l,:] . cw[g,:] + cb[g] ----------------
__global__ void k_embed(const float* __restrict__ items, const float* __restrict__ cw,
                        const float* __restrict__ cb, float* __restrict__ xg)
{
    int bl = blockIdx.x;          // b*Ls + l
    int b  = bl / Ls, l = bl % Ls;
    __shared__ float it[IND];
    if (threadIdx.x < IND) it[threadIdx.x] = items[(size_t)bl * IND + threadIdx.x];
    __syncthreads();
    float i0 = it[0], i1 = it[1], i2 = it[2], i3 = it[3];
    float i4 = it[4], i5 = it[5], i6 = it[6], i7 = it[7];
    float* orow = xg + ((size_t)l * Bz + b) * Gd;
    for (int g = threadIdx.x; g < Gd; g += blockDim.x) {
        const float4* w = reinterpret_cast<const float4*>(cw + (size_t)g * IND);
        float4 w0 = w[0], w1 = w[1];
        float acc = cb[g];
        acc += i0 * w0.x + i1 * w0.y + i2 * w0.z + i3 * w0.w;
        acc += i4 * w1.x + i5 * w1.y + i6 * w1.z + i7 * w1.w;
        orow[g] = acc;
    }
}

// ---------------- tiled NT GEMM: C[m,n] = sum_k A[m,k]*Bw[n,k] (+ bias[n]) ----------------
// BM=128, BN=64, BK=16, 256 threads, 8x4 microtile, double-buffered smem.
__global__ void __launch_bounds__(256) k_gemm_nt64(
    const float* __restrict__ A, const float* __restrict__ Bw,
    const float* __restrict__ bias, float* __restrict__ C,
    int M, int N, int K)
{
    constexpr int BM = 128, BN = 64, BK = 16, TM = 8, TN = 4;
    __shared__ float As[2][BK][BM + 4];
    __shared__ float Bs[2][BK][BN + 4];
    const int tid = threadIdx.x;
    const int tx  = tid & 15;
    const int ty  = tid >> 4;
    const size_t bm = (size_t)blockIdx.x * BM;
    const size_t bn = (size_t)blockIdx.y * BN;

    float acc[TM][TN];
#pragma unroll
    for (int i = 0; i < TM; i++)
#pragma unroll
        for (int j = 0; j < TN; j++) acc[i][j] = 0.0f;

    const int a_row0 = tid >> 2;          // 0..63
    const int a_c4   = (tid & 3) << 2;    // 0,4,8,12

    const float* Aptr0 = A  + (bm + a_row0)      * (size_t)K + a_c4;
    const float* Aptr1 = A  + (bm + a_row0 + 64) * (size_t)K + a_c4;
    const float* Bptr0 = Bw + (bn + a_row0)      * (size_t)K + a_c4;

    float4 af0, af1, bf0;

    auto fetch = [&](int kt) {
        size_t k0 = (size_t)kt * BK;
        af0 = *reinterpret_cast<const float4*>(Aptr0 + k0);
        af1 = *reinterpret_cast<const float4*>(Aptr1 + k0);
        bf0 = *reinterpret_cast<const float4*>(Bptr0 + k0);
    };
    auto stash = [&](int buf) {
        As[buf][a_c4 + 0][a_row0]      = af0.x;
        As[buf][a_c4 + 1][a_row0]      = af0.y;
        As[buf][a_c4 + 2][a_row0]      = af0.z;
        As[buf][a_c4 + 3][a_row0]      = af0.w;
        As[buf][a_c4 + 0][a_row0 + 64] = af1.x;
        As[buf][a_c4 + 1][a_row0 + 64] = af1.y;
        As[buf][a_c4 + 2][a_row0 + 64] = af1.z;
        As[buf][a_c4 + 3][a_row0 + 64] = af1.w;
        Bs[buf][a_c4 + 0][a_row0]      = bf0.x;
        Bs[buf][a_c4 + 1][a_row0]      = bf0.y;
        Bs[buf][a_c4 + 2][a_row0]      = bf0.z;
        Bs[buf][a_c4 + 3][a_row0]      = bf0.w;
    };

    const int NKT = K / BK;
    fetch(0); stash(0);
    __syncthreads();
    for (int kt = 0; kt < NKT; kt++) {
        int cur = kt & 1;
        if (kt + 1 < NKT) fetch(kt + 1);
#pragma unroll
        for (int k = 0; k < BK; k++) {
            float4 a0 = *reinterpret_cast<const float4*>(&As[cur][k][ty * TM]);
            float4 a1 = *reinterpret_cast<const float4*>(&As[cur][k][ty * TM + 4]);
            float4 b0 = *reinterpret_cast<const float4*>(&Bs[cur][k][tx * TN]);
            float a[8] = {a0.x, a0.y, a0.z, a0.w, a1.x, a1.y, a1.z, a1.w};
            float b[4] = {b0.x, b0.y, b0.z, b0.w};
#pragma unroll
            for (int i = 0; i < TM; i++)
#pragma unroll
                for (int j = 0; j < TN; j++)
                    acc[i][j] = fmaf(a[i], b[j], acc[i][j]);
        }
        if (kt + 1 < NKT) {
            stash((kt + 1) & 1);
            __syncthreads();
        }
    }

    float bv[TN];
#pragma unroll
    for (int j = 0; j < TN; j++) bv[j] = bias ? bias[bn + tx * TN + j] : 0.0f;
#pragma unroll
    for (int i = 0; i < TM; i++) {
        size_t m = bm + ty * TM + i;
        float4 o;
        o.x = acc[i][0] + bv[0];
        o.y = acc[i][1] + bv[1];
        o.z = acc[i][2] + bv[2];
        o.w = acc[i][3] + bv[3];
        *reinterpret_cast<float4*>(&C[m * (size_t)N + bn + tx * TN]) = o;
    }
}

// ---------------- GRU gate fusion: h_new from xg, hg (or bhh if hg==null), hprev (or 0) ----------------
__global__ void k_gate(const float* __restrict__ xg, const float* __restrict__ hg,
                       const float* __restrict__ bhh, const float* __restrict__ hprev,
                       float* __restrict__ hout)
{
    int idx = blockIdx.x * blockDim.x + threadIdx.x;   // over Bz*Hd
    int b = idx >> 9;          // / 512
    int j = idx & 511;
    const float* xrow = xg + (size_t)b * Gd;
    float xr = xrow[j], xz = xrow[Hd + j], xn = xrow[2 * Hd + j];
    float hr, hz, hn;
    if (hg) {
        const float* hrow = hg + (size_t)b * Gd;
        hr = hrow[j]; hz = hrow[Hd + j]; hn = hrow[2 * Hd + j];
    } else {
        hr = bhh[j]; hz = bhh[Hd + j]; hn = bhh[2 * Hd + j];
    }
    float hp = hprev ? hprev[idx] : 0.0f;
    float r = sigm_f(xr + hr);
    float z = sigm_f(xz + hz);
    float n = tanh_f(xn + r * hn);
    hout[idx] = n + z * (hp - n);
}

// ---------------- out_seq: one warp per (l,b): sum_k v2[k]*tanh(enc_w3[l,b,k] + A[b,k]) ----------------
__global__ void k_seq(const float* __restrict__ encw3, const float* __restrict__ Abuf,
                      const float* __restrict__ v2, float* __restrict__ out, int t)
{
    int gw   = (blockIdx.x * blockDim.x + threadIdx.x) >> 5;  // 0..Bz*Ls-1, gw = l*Bz + b
    int lane = threadIdx.x & 31;
    int l = gw >> 12;        // / 4096
    int b = gw & 4095;
    const float* e = encw3 + (size_t)gw * Hd;
    const float* a = Abuf  + (size_t)b  * Hd;
    float s = 0.0f;
#pragma unroll 4
    for (int k = lane; k < Hd; k += 32)
        s += v2[k] * tanh_f(e[k] + a[k]);
    for (int o = 16; o; o >>= 1) s += __shfl_xor_sync(0xffffffffu, s, o);
    if (!lane) out[((size_t)b * Ls + t) * Ls + l] = s;
}

// ---------------- out_ori: one warp per b: h_new . wori[j, 512:1024] + bori[j], j=0..5 ----------------
__global__ void k_ori(const float* __restrict__ h, const float* __restrict__ wori,
                      const float* __restrict__ bori, float* __restrict__ out, int t)
{
    int b    = (blockIdx.x * blockDim.x + threadIdx.x) >> 5;  // 0..Bz-1
    int lane = threadIdx.x & 31;
    float s[6] = {0, 0, 0, 0, 0, 0};
    const float* hb = h + (size_t)b * Hd;
    for (int k = lane; k < Hd; k += 32) {
        float hv = hb[k];
#pragma unroll
        for (int j = 0; j < 6; j++)
            s[j] += hv * wori[(size_t)j * Gd + Hd + k];
    }
#pragma unroll
    for (int j = 0; j < 6; j++)
        for (int o = 16; o; o >>= 1) s[j] += __shfl_xor_sync(0xffffffffu, s[j], o);
    if (!lane) {
#pragma unroll
        for (int j = 0; j < 6; j++)
            out[((size_t)b * Ls + t) * 6 + j] = s[j] + bori[j];
    }
}

// ---------------- launch ----------------
extern "C" void kernel_launch(void* const* d_in, const int* in_sizes, int n_in,
                              void* d_out, int out_size)
{
    const float* items    = (const float*)d_in[0];
    const float* dec_in   = (const float*)d_in[1];
    const float* emb_w    = (const float*)d_in[2];
    const float* emb_b    = (const float*)d_in[3];
    const float* enc_wih  = (const float*)d_in[4];
    const float* enc_whh  = (const float*)d_in[5];
    const float* enc_bih  = (const float*)d_in[6];
    const float* enc_bhh  = (const float*)d_in[7];
    // d_in[8] = dec_wih
    const float* dec_wih  = (const float*)d_in[8];
    const float* dec_whh  = (const float*)d_in[9];
    const float* dec_bih  = (const float*)d_in[10];
    const float* dec_bhh  = (const float*)d_in[11];
    // w1, w2 (12, 13) dead
    const float* w3       = (const float*)d_in[14];
    const float* w4       = (const float*)d_in[15];
    // w5 (16), w6 (17), w7 (18), v1 (19) dead
    const float* v2       = (const float*)d_in[20];
    // v3_w (21), v3_b (22) dead
    const float* wori     = (const float*)d_in[23];
    const float* bori     = (const float*)d_in[24];

    float* out_seq = (float*)d_out;                       // (Bz, Ls, Ls)
    float* out_ori = (float*)d_out + (size_t)Bz * Ls * Ls; // (Bz, Ls, 6)

    float* S = nullptr;
    cudaGetSymbolAddress((void**)&S, g_scratch);
    float* XG_ENC  = S + OFF_XG_ENC;
    float* ENC_OUT = S + OFF_ENC_OUT;
    float* ENC_W3  = S + OFF_ENC_W3;
    float* HG      = S + OFF_HG;
    float* XG_DEC  = S + OFF_XG_DEC;
    float* HBUF    = S + OFF_H;
    float* ABUF    = S + OFF_A;
    float* CW      = S + OFF_CW;
    float* CB      = S + OFF_CB;

    // 1. combined embedding+encoder-input weights
    k_combine<<<Gd, 128>>>(enc_wih, emb_w, emb_b, enc_bih, CW, CB);

    // 2. encoder input gates for all (l, b)
    k_embed<<<Bz * Ls, 256>>>(items, CW, CB, XG_ENC);

    // 3. decoder input gates (fixed across steps)
    k_gemm_nt64<<<dim3(Bz / 128, Gd / 64), 256>>>(dec_in, dec_wih, dec_bih, XG_DEC, Bz, Gd, Hd);

    // 4. encoder GRU scan
    for (int t = 0; t < Ls; t++) {
        const float* hp = t ? (ENC_OUT + (size_t)(t - 1) * Bz * Hd) : nullptr;
        if (t)
            k_gemm_nt64<<<dim3(Bz / 128, Gd / 64), 256>>>(hp, enc_whh, enc_bhh, HG, Bz, Gd, Hd);
        k_gate<<<(Bz * Hd) / 256, 256>>>(XG_ENC + (size_t)t * Bz * Gd,
                                         t ? HG : nullptr, enc_bhh, hp,
                                         ENC_OUT + (size_t)t * Bz * Hd);
    }

    // 5. enc_w3 = enc_out @ w3.T  (flattened L*B rows)
    k_gemm_nt64<<<dim3((Ls * Bz) / 128, Hd / 64), 256>>>(ENC_OUT, w3, nullptr, ENC_W3,
                                                         Ls * Bz, Hd, Hd);

    // 6. decoder scan
    const float* hp = ENC_OUT + (size_t)(Ls - 1) * Bz * Hd;
    for (int t = 0; t < Ls; t++) {
        k_gemm_nt64<<<dim3(Bz / 128, Gd / 64), 256>>>(hp, dec_whh, dec_bhh, HG, Bz, Gd, Hd);
        k_gate<<<(Bz * Hd) / 256, 256>>>(XG_DEC, HG, dec_bhh, hp, HBUF);
        k_gemm_nt64<<<dim3(Bz / 128, Hd / 64), 256>>>(HBUF, w4, nullptr, ABUF, Bz, Hd, Hd);
        k_seq<<<(Bz * Ls) / 8, 256>>>(ENC_W3, ABUF, v2, out_seq, t);
        k_ori<<<Bz / 8, 256>>>(HBUF, wori, bori, out_ori, t);
        hp = HBUF;
    }
}

// round 2
// speedup vs baseline: 1.0028x; 1.0028x over previous
#include <cuda_runtime.h>
#include <math.h>

static constexpr int Bz  = 4096;
static constexpr int Ls  = 10;
static constexpr int IND = 8;
static constexpr int Hd  = 512;
static constexpr int Gd  = 1536;   // 3*Hd

// ---------------- scratch (single __device__ array, offsets in floats) ----------------
static constexpr size_t OFF_XG_ENC  = 0;                                   // Ls*Bz*Gd
static constexpr size_t OFF_ENC_OUT = OFF_XG_ENC  + (size_t)Ls*Bz*Gd;      // Ls*Bz*Hd
static constexpr size_t OFF_ENC_W3  = OFF_ENC_OUT + (size_t)Ls*Bz*Hd;      // Ls*Bz*Hd
static constexpr size_t OFF_HG      = OFF_ENC_W3  + (size_t)Ls*Bz*Hd;      // Bz*Gd
static constexpr size_t OFF_XG_DEC  = OFF_HG      + (size_t)Bz*Gd;         // Bz*Gd
static constexpr size_t OFF_H       = OFF_XG_DEC  + (size_t)Bz*Gd;         // Bz*Hd
static constexpr size_t OFF_A       = OFF_H       + (size_t)Bz*Hd;         // Bz*Hd
static constexpr size_t OFF_CW      = OFF_A       + (size_t)Bz*Hd;         // Gd*IND
static constexpr size_t OFF_CB      = OFF_CW      + (size_t)Gd*IND;        // Gd
static constexpr size_t SCRATCH_TOTAL = OFF_CB + Gd;

__device__ float g_scratch[SCRATCH_TOTAL];

// ---------------- math helpers (fp32-accurate enough: few-ulp) ----------------
__device__ __forceinline__ float sigm_f(float x) {
    return 1.0f / (1.0f + __expf(-x));
}
__device__ __forceinline__ float tanh_f(float x) {
    float ax = fabsf(x);
    float t  = __expf(-2.0f * ax);
    float r  = __fdividef(1.0f - t, 1.0f + t);
    return copysignf(r, x);
}

// ---------------- combine: cw = enc_wih @ emb_w (1536x8), cb = enc_wih@emb_b + enc_bih ----------------
__global__ void k_combine(const float* __restrict__ enc_wih, const float* __restrict__ emb_w,
                          const float* __restrict__ emb_b,  const float* __restrict__ enc_bih,
                          float* __restrict__ cw, float* __restrict__ cb)
{
    int g   = blockIdx.x;        // 0..Gd-1
    int tid = threadIdx.x;       // 128 threads
    float p[IND + 1];
#pragma unroll
    for (int i = 0; i <= IND; i++) p[i] = 0.0f;
    const float* wr = enc_wih + (size_t)g * Hd;
    for (int k = tid; k < Hd; k += 128) {
        float wv = wr[k];
#pragma unroll
        for (int i = 0; i < IND; i++) p[i] += wv * emb_w[(size_t)k * IND + i];
        p[IND] += wv * emb_b[k];
    }
#pragma unroll
    for (int i = 0; i <= IND; i++)
        for (int o = 16; o; o >>= 1) p[i] += __shfl_xor_sync(0xffffffffu, p[i], o);
    __shared__ float red[IND + 1][4];
    int wid = tid >> 5, lane = tid & 31;
    if (!lane) {
#pragma unroll
        for (int i = 0; i <= IND; i++) red[i][wid] = p[i];
    }
    __syncthreads();
    if (tid <= IND) {
        float s = red[tid][0] + red[tid][1] + red[tid][2] + red[tid][3];
        if (tid < IND) cw[(size_t)g * IND + tid] = s;
        else           cb[g] = s + enc_bih[g];
    }
}

// ---------------- embed: xg[(l*Bz+b)*Gd + g] = items[b,l,:] . cw[g,:] + cb[g] ----------------
__global__ void k_embed(const float* __restrict__ items, const float* __restrict__ cw,
                        const float* __restrict__ cb, float* __restrict__ xg)
{
    int bl = blockIdx.x;          // b*Ls + l
    int b  = bl / Ls, l = bl % Ls;
    __shared__ float it[IND];
    if (threadIdx.x < IND) it[threadIdx.x] = items[(size_t)bl * IND + threadIdx.x];
    __syncthreads();
    float i0 = it[0], i1 = it[1], i2 = it[2], i3 = it[3];
    float i4 = it[4], i5 = it[5], i6 = it[6], i7 = it[7];
    float* orow = xg + ((size_t)l * Bz + b) * Gd;
    for (int g = threadIdx.x; g < Gd; g += blockDim.x) {
        const float4* w = reinterpret_cast<const float4*>(cw + (size_t)g * IND);
        float4 w0 = w[0], w1 = w[1];
        float acc = cb[g];
        acc += i0 * w0.x + i1 * w0.y + i2 * w0.z + i3 * w0.w;
        acc += i4 * w1.x + i5 * w1.y + i6 * w1.z + i7 * w1.w;
        orow[g] = acc;
    }
}

// ---------------- tiled NT GEMM: C[m,n] = sum_k A[m,k]*Bw[n,k] (+ bias[n]) ----------------
// BM=128, BN=64, BK=16, 256 threads, 8x4 microtile, double-buffered smem.
__global__ void __launch_bounds__(256) k_gemm_nt64(
    const float* __restrict__ A, const float* __restrict__ Bw,
    const float* __restrict__ bias, float* __restrict__ C,
    int M, int N, int K)
{
    constexpr int BM = 128, BN = 64, BK = 16, TM = 8, TN = 4;
    __shared__ float As[2][BK][BM + 4];
    __shared__ float Bs[2][BK][BN + 4];
    const int tid = threadIdx.x;
    const int tx  = tid & 15;
    const int ty  = tid >> 4;
    const size_t bm = (size_t)blockIdx.x * BM;
    const size_t bn = (size_t)blockIdx.y * BN;

    float acc[TM][TN];
#pragma unroll
    for (int i = 0; i < TM; i++)
#pragma unroll
        for (int j = 0; j < TN; j++) acc[i][j] = 0.0f;

    const int a_row0 = tid >> 2;          // 0..63
    const int a_c4   = (tid & 3) << 2;    // 0,4,8,12

    const float* Aptr0 = A  + (bm + a_row0)      * (size_t)K + a_c4;
    const float* Aptr1 = A  + (bm + a_row0 + 64) * (size_t)K + a_c4;
    const float* Bptr0 = Bw + (bn + a_row0)      * (size_t)K + a_c4;

    float4 af0, af1, bf0;

    auto fetch = [&](int kt) {
        size_t k0 = (size_t)kt * BK;
        af0 = *reinterpret_cast<const float4*>(Aptr0 + k0);
        af1 = *reinterpret_cast<const float4*>(Aptr1 + k0);
        bf0 = *reinterpret_cast<const float4*>(Bptr0 + k0);
    };
    auto stash = [&](int buf) {
        As[buf][a_c4 + 0][a_row0]      = af0.x;
        As[buf][a_c4 + 1][a_row0]      = af0.y;
        As[buf][a_c4 + 2][a_row0]      = af0.z;
        As[buf][a_c4 + 3][a_row0]      = af0.w;
        As[buf][a_c4 + 0][a_row0 + 64] = af1.x;
        As[buf][a_c4 + 1][a_row0 + 64] = af1.y;
        As[buf][a_c4 + 2][a_row0 + 64] = af1.z;
        As[buf][a_c4 + 3][a_row0 + 64] = af1.w;
        Bs[buf][a_c4 + 0][a_row0]      = bf0.x;
        Bs[buf][a_c4 + 1][a_row0]      = bf0.y;
        Bs[buf][a_c4 + 2][a_row0]      = bf0.z;
        Bs[buf][a_c4 + 3][a_row0]      = bf0.w;
    };

    const int NKT = K / BK;
    fetch(0); stash(0);
    __syncthreads();
    for (int kt = 0; kt < NKT; kt++) {
        int cur = kt & 1;
        if (kt + 1 < NKT) fetch(kt + 1);
#pragma unroll
        for (int k = 0; k < BK; k++) {
            float4 a0 = *reinterpret_cast<const float4*>(&As[cur][k][ty * TM]);
            float4 a1 = *reinterpret_cast<const float4*>(&As[cur][k][ty * TM + 4]);
            float4 b0 = *reinterpret_cast<const float4*>(&Bs[cur][k][tx * TN]);
            float a[8] = {a0.x, a0.y, a0.z, a0.w, a1.x, a1.y, a1.z, a1.w};
            float b[4] = {b0.x, b0.y, b0.z, b0.w};
#pragma unroll
            for (int i = 0; i < TM; i++)
#pragma unroll
                for (int j = 0; j < TN; j++)
                    acc[i][j] = fmaf(a[i], b[j], acc[i][j]);
        }
        if (kt + 1 < NKT) {
            stash((kt + 1) & 1);
            __syncthreads();
        }
    }

    float bv[TN];
#pragma unroll
    for (int j = 0; j < TN; j++) bv[j] = bias ? bias[bn + tx * TN + j] : 0.0f;
#pragma unroll
    for (int i = 0; i < TM; i++) {
        size_t m = bm + ty * TM + i;
        float4 o;
        o.x = acc[i][0] + bv[0];
        o.y = acc[i][1] + bv[1];
        o.z = acc[i][2] + bv[2];
        o.w = acc[i][3] + bv[3];
        *reinterpret_cast<float4*>(&C[m * (size_t)N + bn + tx * TN]) = o;
    }
}

// ---------------- GRU gate fusion: h_new from xg, hg (or bhh if hg==null), hprev (or 0) ----------------
__global__ void k_gate(const float* __restrict__ xg, const float* __restrict__ hg,
                       const float* __restrict__ bhh, const float* __restrict__ hprev,
                       float* __restrict__ hout)
{
    int idx = blockIdx.x * blockDim.x + threadIdx.x;   // over Bz*Hd
    int b = idx >> 9;          // / 512
    int j = idx & 511;
    const float* xrow = xg + (size_t)b * Gd;
    float xr = xrow[j], xz = xrow[Hd + j], xn = xrow[2 * Hd + j];
    float hr, hz, hn;
    if (hg) {
        const float* hrow = hg + (size_t)b * Gd;
        hr = hrow[j]; hz = hrow[Hd + j]; hn = hrow[2 * Hd + j];
    } else {
        hr = bhh[j]; hz = bhh[Hd + j]; hn = bhh[2 * Hd + j];
    }
    float hp = hprev ? hprev[idx] : 0.0f;
    float r = sigm_f(xr + hr);
    float z = sigm_f(xz + hz);
    float n = tanh_f(xn + r * hn);
    hout[idx] = n + z * (hp - n);
}

// ---------------- out_seq: one warp per (l,b): sum_k v2[k]*tanh(enc_w3[l,b,k] + A[b,k]) ----------------
__global__ void k_seq(const float* __restrict__ encw3, const float* __restrict__ Abuf,
                      const float* __restrict__ v2, float* __restrict__ out, int t)
{
    int gw   = (blockIdx.x * blockDim.x + threadIdx.x) >> 5;  // 0..Bz*Ls-1, gw = l*Bz + b
    int lane = threadIdx.x & 31;
    int l = gw >> 12;        // / 4096
    int b = gw & 4095;
    const float* e = encw3 + (size_t)gw * Hd;
    const float* a = Abuf  + (size_t)b  * Hd;
    float s = 0.0f;
#pragma unroll 4
    for (int k = lane; k < Hd; k += 32)
        s += v2[k] * tanh_f(e[k] + a[k]);
    for (int o = 16; o; o >>= 1) s += __shfl_xor_sync(0xffffffffu, s, o);
    if (!lane) out[((size_t)b * Ls + t) * Ls + l] = s;
}

// ---------------- out_ori: one warp per b: h_new . wori[j, 512:1024] + bori[j], j=0..5 ----------------
__global__ void k_ori(const float* __restrict__ h, const float* __restrict__ wori,
                      const float* __restrict__ bori, float* __restrict__ out, int t)
{
    int b    = (blockIdx.x * blockDim.x + threadIdx.x) >> 5;  // 0..Bz-1
    int lane = threadIdx.x & 31;
    float s[6] = {0, 0, 0, 0, 0, 0};
    const float* hb = h + (size_t)b * Hd;
    for (int k = lane; k < Hd; k += 32) {
        float hv = hb[k];
#pragma unroll
        for (int j = 0; j < 6; j++)
            s[j] += hv * wori[(size_t)j * Gd + Hd + k];
    }
#pragma unroll
    for (int j = 0; j < 6; j++)
        for (int o = 16; o; o >>= 1) s[j] += __shfl_xor_sync(0xffffffffu, s[j], o);
    if (!lane) {
#pragma unroll
        for (int j = 0; j < 6; j++)
            out[((size_t)b * Ls + t) * 6 + j] = s[j] + bori[j];
    }
}

// ---------------- launch ----------------
extern "C" void kernel_launch(void* const* d_in, const int* in_sizes, int n_in,
                              void* d_out, int out_size)
{
    const float* items    = (const float*)d_in[0];
    const float* dec_in   = (const float*)d_in[1];
    const float* emb_w    = (const float*)d_in[2];
    const float* emb_b    = (const float*)d_in[3];
    const float* enc_wih  = (const float*)d_in[4];
    const float* enc_whh  = (const float*)d_in[5];
    const float* enc_bih  = (const float*)d_in[6];
    const float* enc_bhh  = (const float*)d_in[7];
    // d_in[8] = dec_wih
    const float* dec_wih  = (const float*)d_in[8];
    const float* dec_whh  = (const float*)d_in[9];
    const float* dec_bih  = (const float*)d_in[10];
    const float* dec_bhh  = (const float*)d_in[11];
    // w1, w2 (12, 13) dead
    const float* w3       = (const float*)d_in[14];
    const float* w4       = (const float*)d_in[15];
    // w5 (16), w6 (17), w7 (18), v1 (19) dead
    const float* v2       = (const float*)d_in[20];
    // v3_w (21), v3_b (22) dead
    const float* wori     = (const float*)d_in[23];
    const float* bori     = (const float*)d_in[24];

    float* out_seq = (float*)d_out;                       // (Bz, Ls, Ls)
    float* out_ori = (float*)d_out + (size_t)Bz * Ls * Ls; // (Bz, Ls, 6)

    float* S = nullptr;
    cudaGetSymbolAddress((void**)&S, g_scratch);
    float* XG_ENC  = S + OFF_XG_ENC;
    float* ENC_OUT = S + OFF_ENC_OUT;
    float* ENC_W3  = S + OFF_ENC_W3;
    float* HG      = S + OFF_HG;
    float* XG_DEC  = S + OFF_XG_DEC;
    float* HBUF    = S + OFF_H;
    float* ABUF    = S + OFF_A;
    float* CW      = S + OFF_CW;
    float* CB      = S + OFF_CB;

    // 1. combined embedding+encoder-input weights
    k_combine<<<Gd, 128>>>(enc_wih, emb_w, emb_b, enc_bih, CW, CB);

    // 2. encoder input gates for all (l, b)
    k_embed<<<Bz * Ls, 256>>>(items, CW, CB, XG_ENC);

    // 3. decoder input gates (fixed across steps)
    k_gemm_nt64<<<dim3(Bz / 128, Gd / 64), 256>>>(dec_in, dec_wih, dec_bih, XG_DEC, Bz, Gd, Hd);

    // 4. encoder GRU scan
    for (int t = 0; t < Ls; t++) {
        const float* hp = t ? (ENC_OUT + (size_t)(t - 1) * Bz * Hd) : nullptr;
        if (t)
            k_gemm_nt64<<<dim3(Bz / 128, Gd / 64), 256>>>(hp, enc_whh, enc_bhh, HG, Bz, Gd, Hd);
        k_gate<<<(Bz * Hd) / 256, 256>>>(XG_ENC + (size_t)t * Bz * Gd,
                                         t ? HG : nullptr, enc_bhh, hp,
                                         ENC_OUT + (size_t)t * Bz * Hd);
    }

    // 5. enc_w3 = enc_out @ w3.T  (flattened L*B rows)
    k_gemm_nt64<<<dim3((Ls * Bz) / 128, Hd / 64), 256>>>(ENC_OUT, w3, nullptr, ENC_W3,
                                                         Ls * Bz, Hd, Hd);

    // 6. decoder scan
    const float* hp = ENC_OUT + (size_t)(Ls - 1) * Bz * Hd;
    for (int t = 0; t < Ls; t++) {
        k_gemm_nt64<<<dim3(Bz / 128, Gd / 64), 256>>>(hp, dec_whh, dec_bhh, HG, Bz, Gd, Hd);
        k_gate<<<(Bz * Hd) / 256, 256>>>(XG_DEC, HG, dec_bhh, hp, HBUF);
        k_gemm_nt64<<<dim3(Bz / 128, Hd / 64), 256>>>(HBUF, w4, nullptr, ABUF, Bz, Hd, Hd);
        k_seq<<<(Bz * Ls) / 8, 256>>>(ENC_W3, ABUF, v2, out_seq, t);
        k_ori<<<Bz / 8, 256>>>(HBUF, wori, bori, out_ori, t);
        hp = HBUF;
    }
}

// round 4
// speedup vs baseline: 1.6785x; 1.6739x over previous
#include <cuda_runtime.h>
#include <cuda_bf16.h>
#include <cstdint>
#include <math.h>

static constexpr int Bz  = 4096;
static constexpr int Ls  = 10;
static constexpr int IND = 8;
static constexpr int Hd  = 512;
static constexpr int Gd  = 1536;   // 3*Hd
static constexpr int K2  = 1024;   // split row length in bf16: [hi 512 | lo 512]

// ---------------- scratch (offsets in floats; bf16 buffers count as half) ----------------
static constexpr size_t OFF_XG_ENC  = 0;                                     // Ls*Bz*Gd f32
static constexpr size_t OFF_HG      = OFF_XG_ENC  + (size_t)Ls*Bz*Gd;        // Bz*Gd f32
static constexpr size_t OFF_XG_DEC  = OFF_HG      + (size_t)Bz*Gd;           // Bz*Gd f32
static constexpr size_t OFF_ENC_OUT = OFF_XG_DEC  + (size_t)Bz*Gd;           // Ls*Bz*Hd f32
static constexpr size_t OFF_ENC2    = OFF_ENC_OUT + (size_t)Ls*Bz*Hd;        // Ls*Bz*K2 bf16
static constexpr size_t OFF_ENC_W3  = OFF_ENC2    + (size_t)Ls*Bz*K2/2;      // Ls*Bz*Hd f32
static constexpr size_t OFF_H_ALL   = OFF_ENC_W3  + (size_t)Ls*Bz*Hd;        // Ls*Bz*Hd f32
static constexpr size_t OFF_A_ALL   = OFF_H_ALL   + (size_t)Ls*Bz*Hd;        // Ls*Bz*Hd f32
static constexpr size_t OFF_H2      = OFF_A_ALL   + (size_t)Ls*Bz*Hd;        // Bz*K2 bf16
static constexpr size_t OFF_DEC2    = OFF_H2      + (size_t)Bz*K2/2;         // Bz*K2 bf16
static constexpr size_t OFF_WHHE2   = OFF_DEC2    + (size_t)Bz*K2/2;         // Gd*K2 bf16
static constexpr size_t OFF_WHHD2   = OFF_WHHE2   + (size_t)Gd*K2/2;
static constexpr size_t OFF_WIHD2   = OFF_WHHD2   + (size_t)Gd*K2/2;
static constexpr size_t OFF_W32     = OFF_WIHD2   + (size_t)Gd*K2/2;         // Hd*K2 bf16
static constexpr size_t OFF_W42     = OFF_W32     + (size_t)Hd*K2/2;
static constexpr size_t OFF_CW      = OFF_W42     + (size_t)Hd*K2/2;         // Gd*IND f32
static constexpr size_t OFF_CB      = OFF_CW      + (size_t)Gd*IND;          // Gd f32
static constexpr size_t SCRATCH_TOTAL = OFF_CB + Gd;

__device__ __align__(1024) float g_scratch[SCRATCH_TOTAL];

// ---------------- math helpers ----------------
__device__ __forceinline__ float sigm_f(float x) { return 1.0f / (1.0f + __expf(-x)); }
__device__ __forceinline__ float tanh_f(float x) {
    float ax = fabsf(x);
    float t  = __expf(-2.0f * ax);
    float r  = __fdividef(1.0f - t, 1.0f + t);
    return copysignf(r, x);
}

// ---------------- PTX helpers (all baseline sm_80-era, valid on sm_103) ----------------
__device__ __forceinline__ uint32_t smem_u32(const void* p) {
    uint32_t a;
    asm("{ .reg .u64 t; cvta.to.shared.u64 t, %1; cvt.u32.u64 %0, t; }" : "=r"(a) : "l"(p));
    return a;
}
__device__ __forceinline__ void cp16(uint32_t s, const void* g) {
    asm volatile("cp.async.cg.shared.global [%0], [%1], 16;" :: "r"(s), "l"(g) : "memory");
}
__device__ __forceinline__ void ldm_x4(uint32_t& r0, uint32_t& r1, uint32_t& r2, uint32_t& r3,
                                       uint32_t addr) {
    asm volatile("ldmatrix.sync.aligned.m8n8.x4.shared.b16 {%0,%1,%2,%3}, [%4];"
                 : "=r"(r0), "=r"(r1), "=r"(r2), "=r"(r3) : "r"(addr));
}
__device__ __forceinline__ void mma16816(float* c, const uint32_t* a, uint32_t b0, uint32_t b1) {
    asm volatile("mma.sync.aligned.m16n8k16.row.col.f32.bf16.bf16.f32 "
                 "{%0,%1,%2,%3}, {%4,%5,%6,%7}, {%8,%9}, {%0,%1,%2,%3};"
                 : "+f"(c[0]), "+f"(c[1]), "+f"(c[2]), "+f"(c[3])
                 : "r"(a[0]), "r"(a[1]), "r"(a[2]), "r"(a[3]), "r"(b0), "r"(b1));
}

// ---------------- bf16x3 tensor-core GEMM: C[M,N] = A @ B^T (+bias) ----------------
// A2[M,K2], B2[N,K2] bf16 split rows [hi(512)|lo(512)].
// 48 virtual K-tiles of 32: pass0 Ahi*Bhi, pass1 Ahi*Blo, pass2 Alo*Bhi.
// Tile 128x128, 256 threads (8 warps of 32x64), 2-stage cp.async double buffer.
// Smem rows padded to 80B: bank-rotation 20*r mod 32 -> conflict-free ldmatrix.
static constexpr int TILE_B = 10240;     // one buffer: 128 rows * 80 bytes

__global__ void __launch_bounds__(256) k_gemm_mma(
    const __nv_bfloat16* __restrict__ A2, const __nv_bfloat16* __restrict__ B2,
    const float* __restrict__ bias, float* __restrict__ C, int N)
{
    __shared__ __nv_bfloat16 As[2][128][40];
    __shared__ __nv_bfloat16 Bs[2][128][40];
    const int tid  = threadIdx.x;
    const int wid  = tid >> 5, lane = tid & 31;
    const int wm   = wid & 3;          // M-warp: rows wm*32
    const int wn   = wid >> 2;         // N-warp: cols wn*64
    const size_t bm = (size_t)blockIdx.x * 128;
    const size_t bn = (size_t)blockIdx.y * 128;

    const uint32_t sA = smem_u32(As);
    const uint32_t sB = smem_u32(Bs);

    float acc[2][8][4];
#pragma unroll
    for (int i = 0; i < 2; i++)
#pragma unroll
        for (int j = 0; j < 8; j++)
#pragma unroll
            for (int q = 0; q < 4; q++) acc[i][j][q] = 0.0f;

    // load mapping: each thread moves 2 x 16B per operand tile
    const int lrow = tid >> 2;             // 0..63
    const int lcol = (tid & 3) << 4;       // byte 0,16,32,48
    const char* aG = (const char*)A2 + (bm + lrow) * 2048 + lcol;
    const char* bG = (const char*)B2 + (bn + lrow) * 2048 + lcol;
    const uint32_t dA = sA + lrow * 80 + lcol;
    const uint32_t dB = sB + lrow * 80 + lcol;

#define LOAD_TILE(kt, buf)                                                        \
    {                                                                             \
        int pass_ = (kt) >> 4, kk_ = (kt) & 15;                                   \
        int ao_ = ((pass_ == 2) ? 1024 : 0) + kk_ * 64;                           \
        int bo_ = ((pass_ == 1) ? 1024 : 0) + kk_ * 64;                           \
        cp16(dA + (buf) * TILE_B,            aG + ao_);                           \
        cp16(dA + (buf) * TILE_B + 64 * 80,  aG + 64 * 2048 + ao_);               \
        cp16(dB + (buf) * TILE_B,            bG + bo_);                           \
        cp16(dB + (buf) * TILE_B + 64 * 80,  bG + 64 * 2048 + bo_);               \
        asm volatile("cp.async.commit_group;" ::: "memory");                      \
    }

    LOAD_TILE(0, 0);

    const uint32_t mA0 = sA + (wm * 32 + (lane & 15)) * 80 + ((lane >> 4) << 4);
    const uint32_t mB0 = sB + (wn * 64 + (lane & 15)) * 80 + ((lane >> 4) << 4);

    for (int kt = 0; kt < 48; kt++) {
        int buf = kt & 1;
        if (kt < 47) {
            LOAD_TILE(kt + 1, buf ^ 1);
            asm volatile("cp.async.wait_group 1;" ::: "memory");
        } else {
            asm volatile("cp.async.wait_group 0;" ::: "memory");
        }
        __syncthreads();

#pragma unroll
        for (int ks = 0; ks < 2; ks++) {
            uint32_t a[2][4], b[4][4];
#pragma unroll
            for (int mf = 0; mf < 2; mf++)
                ldm_x4(a[mf][0], a[mf][1], a[mf][2], a[mf][3],
                       mA0 + buf * TILE_B + mf * 16 * 80 + ks * 32);
#pragma unroll
            for (int nb = 0; nb < 4; nb++)
                ldm_x4(b[nb][0], b[nb][1], b[nb][2], b[nb][3],
                       mB0 + buf * TILE_B + nb * 16 * 80 + ks * 32);
#pragma unroll
            for (int mf = 0; mf < 2; mf++)
#pragma unroll
                for (int nb = 0; nb < 4; nb++) {
                    mma16816(acc[mf][2 * nb + 0], a[mf], b[nb][0], b[nb][2]);
                    mma16816(acc[mf][2 * nb + 1], a[mf], b[nb][1], b[nb][3]);
                }
        }
        __syncthreads();
    }
#undef LOAD_TILE

    // epilogue
#pragma unroll
    for (int mf = 0; mf < 2; mf++) {
#pragma unroll
        for (int nf = 0; nf < 8; nf++) {
            size_t r0 = bm + wm * 32 + mf * 16 + (lane >> 2);
            int    c0 = (int)bn + wn * 64 + nf * 8 + (lane & 3) * 2;
            float bv0 = 0.f, bv1 = 0.f;
            if (bias) { bv0 = bias[c0]; bv1 = bias[c0 + 1]; }
            float2 o0 = make_float2(acc[mf][nf][0] + bv0, acc[mf][nf][1] + bv1);
            float2 o1 = make_float2(acc[mf][nf][2] + bv0, acc[mf][nf][3] + bv1);
            *reinterpret_cast<float2*>(&C[r0 * (size_t)N + c0])       = o0;
            *reinterpret_cast<float2*>(&C[(r0 + 8) * (size_t)N + c0]) = o1;
        }
    }
}

// ---------------- split: f32[rows x 512] -> bf16 [rows x 1024] (hi|lo) ----------------
__global__ void k_split(const float* __restrict__ in, __nv_bfloat16* __restrict__ out)
{
    size_t idx = (size_t)blockIdx.x * blockDim.x + threadIdx.x;
    size_t r = idx >> 9; int j = (int)(idx & 511);
    float v = in[idx];
    __nv_bfloat16 hi = __float2bfloat16(v);
    float lo = v - __bfloat162float(hi);
    out[r * K2 + j]       = hi;
    out[r * K2 + 512 + j] = __float2bfloat16(lo);
}

// ---------------- combine: cw = enc_wih @ emb_w, cb = enc_wih@emb_b + enc_bih ----------------
__global__ void k_combine(const float* __restrict__ enc_wih, const float* __restrict__ emb_w,
                          const float* __restrict__ emb_b,  const float* __restrict__ enc_bih,
                          float* __restrict__ cw, float* __restrict__ cb)
{
    int g = blockIdx.x, tid = threadIdx.x;
    float p[IND + 1];
#pragma unroll
    for (int i = 0; i <= IND; i++) p[i] = 0.0f;
    const float* wr = enc_wih + (size_t)g * Hd;
    for (int k = tid; k < Hd; k += 128) {
        float wv = wr[k];
#pragma unroll
        for (int i = 0; i < IND; i++) p[i] += wv * emb_w[(size_t)k * IND + i];
        p[IND] += wv * emb_b[k];
    }
#pragma unroll
    for (int i = 0; i <= IND; i++)
        for (int o = 16; o; o >>= 1) p[i] += __shfl_xor_sync(0xffffffffu, p[i], o);
    __shared__ float red[IND + 1][4];
    int wid = tid >> 5, lane = tid & 31;
    if (!lane)
#pragma unroll
        for (int i = 0; i <= IND; i++) red[i][wid] = p[i];
    __syncthreads();
    if (tid <= IND) {
        float s = red[tid][0] + red[tid][1] + red[tid][2] + red[tid][3];
        if (tid < IND) cw[(size_t)g * IND + tid] = s;
        else           cb[g] = s + enc_bih[g];
    }
}

// ---------------- embed ----------------
__global__ void k_embed(const float* __restrict__ items, const float* __restrict__ cw,
                        const float* __restrict__ cb, float* __restrict__ xg)
{
    int bl = blockIdx.x;
    int b = bl / Ls, l = bl % Ls;
    __shared__ float it[IND];
    if (threadIdx.x < IND) it[threadIdx.x] = items[(size_t)bl * IND + threadIdx.x];
    __syncthreads();
    float i0 = it[0], i1 = it[1], i2 = it[2], i3 = it[3];
    float i4 = it[4], i5 = it[5], i6 = it[6], i7 = it[7];
    float* orow = xg + ((size_t)l * Bz + b) * Gd;
    for (int g = threadIdx.x; g < Gd; g += blockDim.x) {
        const float4* w = reinterpret_cast<const float4*>(cw + (size_t)g * IND);
        float4 w0 = w[0], w1 = w[1];
        float acc = cb[g];
        acc += i0 * w0.x + i1 * w0.y + i2 * w0.z + i3 * w0.w;
        acc += i4 * w1.x + i5 * w1.y + i6 * w1.z + i7 * w1.w;
        orow[g] = acc;
    }
}

// ---------------- GRU gate (+ bf16 split write of h_new) ----------------
__global__ void k_gate(const float* __restrict__ xg, const float* __restrict__ hg,
                       const float* __restrict__ bhh, const float* __restrict__ hprev,
                       float* __restrict__ hout, __nv_bfloat16* __restrict__ hsplit)
{
    int idx = blockIdx.x * blockDim.x + threadIdx.x;
    int b = idx >> 9, j = idx & 511;
    const float* xrow = xg + (size_t)b * Gd;
    float xr = xrow[j], xz = xrow[Hd + j], xn = xrow[2 * Hd + j];
    float hr, hz, hn;
    if (hg) {
        const float* hrow = hg + (size_t)b * Gd;
        hr = hrow[j]; hz = hrow[Hd + j]; hn = hrow[2 * Hd + j];
    } else {
        hr = bhh[j]; hz = bhh[Hd + j]; hn = bhh[2 * Hd + j];
    }
    float hp = hprev ? hprev[idx] : 0.0f;
    float r = sigm_f(xr + hr);
    float z = sigm_f(xz + hz);
    float n = tanh_f(xn + r * hn);
    float v = n + z * (hp - n);
    hout[idx] = v;
    __nv_bfloat16 hi = __float2bfloat16(v);
    float lo = v - __bfloat162float(hi);
    hsplit[(size_t)b * K2 + j]       = hi;
    hsplit[(size_t)b * K2 + 512 + j] = __float2bfloat16(lo);
}

// ---------------- batched out_seq over all (t, l): one block per b ----------------
__global__ void __launch_bounds__(256) k_seq_all(
    const float* __restrict__ encw3, const float* __restrict__ A_all,
    const float* __restrict__ v2, float* __restrict__ out)
{
    int b = blockIdx.x, tid = threadIdx.x;
    int wid = tid >> 5, lane = tid & 31;
    __shared__ float Ash[Ls][Hd];
    __shared__ float v2s[Hd];
    __shared__ float red[8][Ls];
    for (int i = tid; i < Hd; i += 256) v2s[i] = v2[i];
    for (int t = 0; t < Ls; t++)
        for (int i = tid; i < Hd; i += 256)
            Ash[t][i] = A_all[((size_t)t * Bz + b) * Hd + i];
    __syncthreads();

    for (int l = 0; l < Ls; l++) {
        const float* e = encw3 + ((size_t)l * Bz + b) * Hd;
        float s[Ls];
#pragma unroll
        for (int t = 0; t < Ls; t++) s[t] = 0.0f;
#pragma unroll
        for (int it = 0; it < 2; it++) {
            int k = tid + it * 256;
            float ek = e[k], vk = v2s[k];
#pragma unroll
            for (int t = 0; t < Ls; t++) s[t] += vk * tanh_f(ek + Ash[t][k]);
        }
#pragma unroll
        for (int t = 0; t < Ls; t++)
            for (int o = 16; o; o >>= 1) s[t] += __shfl_xor_sync(0xffffffffu, s[t], o);
        if (!lane)
#pragma unroll
            for (int t = 0; t < Ls; t++) red[wid][t] = s[t];
        __syncthreads();
        if (tid < Ls) {
            float tot = 0.0f;
#pragma unroll
            for (int w = 0; w < 8; w++) tot += red[w][tid];
            out[((size_t)b * Ls + tid) * Ls + l] = tot;
        }
        __syncthreads();
    }
}

// ---------------- batched out_ori: one warp per (t, b) ----------------
__global__ void k_ori_all(const float* __restrict__ H_all, const float* __restrict__ wori,
                          const float* __restrict__ bori, float* __restrict__ out)
{
    int gw   = (blockIdx.x * blockDim.x + threadIdx.x) >> 5;  // t*Bz + b
    int lane = threadIdx.x & 31;
    int t = gw >> 12, b = gw & 4095;
    float s[6] = {0, 0, 0, 0, 0, 0};
    const float* hb = H_all + ((size_t)t * Bz + b) * Hd;
    for (int k = lane; k < Hd; k += 32) {
        float hv = hb[k];
#pragma unroll
        for (int j = 0; j < 6; j++) s[j] += hv * wori[(size_t)j * Gd + Hd + k];
    }
#pragma unroll
    for (int j = 0; j < 6; j++)
        for (int o = 16; o; o >>= 1) s[j] += __shfl_xor_sync(0xffffffffu, s[j], o);
    if (!lane)
#pragma unroll
        for (int j = 0; j < 6; j++)
            out[((size_t)b * Ls + t) * 6 + j] = s[j] + bori[j];
}

// ---------------- launch ----------------
extern "C" void kernel_launch(void* const* d_in, const int* in_sizes, int n_in,
                              void* d_out, int out_size)
{
    const float* items    = (const float*)d_in[0];
    const float* dec_in   = (const float*)d_in[1];
    const float* emb_w    = (const float*)d_in[2];
    const float* emb_b    = (const float*)d_in[3];
    const float* enc_wih  = (const float*)d_in[4];
    const float* enc_whh  = (const float*)d_in[5];
    const float* enc_bih  = (const float*)d_in[6];
    const float* enc_bhh  = (const float*)d_in[7];
    const float* dec_wih  = (const float*)d_in[8];
    const float* dec_whh  = (const float*)d_in[9];
    const float* dec_bih  = (const float*)d_in[10];
    const float* dec_bhh  = (const float*)d_in[11];
    const float* w3       = (const float*)d_in[14];
    const float* w4       = (const float*)d_in[15];
    const float* v2       = (const float*)d_in[20];
    const float* wori     = (const float*)d_in[23];
    const float* bori     = (const float*)d_in[24];

    float* out_seq = (float*)d_out;                        // (Bz, Ls, Ls)
    float* out_ori = (float*)d_out + (size_t)Bz * Ls * Ls; // (Bz, Ls, 6)

    float* S = nullptr;
    cudaGetSymbolAddress((void**)&S, g_scratch);
    float* XG_ENC  = S + OFF_XG_ENC;
    float* HG      = S + OFF_HG;
    float* XG_DEC  = S + OFF_XG_DEC;
    float* ENC_OUT = S + OFF_ENC_OUT;
    float* ENC_W3  = S + OFF_ENC_W3;
    float* H_ALL   = S + OFF_H_ALL;
    float* A_ALL   = S + OFF_A_ALL;
    float* CW      = S + OFF_CW;
    float* CB      = S + OFF_CB;
    __nv_bfloat16* ENC2  = (__nv_bfloat16*)(S + OFF_ENC2);
    __nv_bfloat16* H2    = (__nv_bfloat16*)(S + OFF_H2);
    __nv_bfloat16* DEC2  = (__nv_bfloat16*)(S + OFF_DEC2);
    __nv_bfloat16* WHHE2 = (__nv_bfloat16*)(S + OFF_WHHE2);
    __nv_bfloat16* WHHD2 = (__nv_bfloat16*)(S + OFF_WHHD2);
    __nv_bfloat16* WIHD2 = (__nv_bfloat16*)(S + OFF_WIHD2);
    __nv_bfloat16* W32   = (__nv_bfloat16*)(S + OFF_W32);
    __nv_bfloat16* W42   = (__nv_bfloat16*)(S + OFF_W42);

    // weight + decoder-input splits
    k_split<<<(Gd * Hd) / 256, 256>>>(enc_whh, WHHE2);
    k_split<<<(Gd * Hd) / 256, 256>>>(dec_whh, WHHD2);
    k_split<<<(Gd * Hd) / 256, 256>>>(dec_wih, WIHD2);
    k_split<<<(Hd * Hd) / 256, 256>>>(w3, W32);
    k_split<<<(Hd * Hd) / 256, 256>>>(w4, W42);
    k_split<<<(Bz * Hd) / 256, 256>>>(dec_in, DEC2);

    // encoder input gates
    k_combine<<<Gd, 128>>>(enc_wih, emb_w, emb_b, enc_bih, CW, CB);
    k_embed<<<Bz * Ls, 256>>>(items, CW, CB, XG_ENC);

    // decoder input gates (step-invariant)
    k_gemm_mma<<<dim3(Bz / 128, Gd / 128), 256>>>(DEC2, WIHD2, dec_bih, XG_DEC, Gd);

    // encoder GRU scan
    for (int t = 0; t < Ls; t++) {
        const float* hp = t ? (ENC_OUT + (size_t)(t - 1) * Bz * Hd) : nullptr;
        if (t)
            k_gemm_mma<<<dim3(Bz / 128, Gd / 128), 256>>>(
                ENC2 + (size_t)(t - 1) * Bz * K2, WHHE2, enc_bhh, HG, Gd);
        k_gate<<<(Bz * Hd) / 256, 256>>>(XG_ENC + (size_t)t * Bz * Gd,
                                         t ? HG : nullptr, enc_bhh, hp,
                                         ENC_OUT + (size_t)t * Bz * Hd,
                                         ENC2 + (size_t)t * Bz * K2);
    }

    // enc_w3 = enc_out @ w3^T  (all Ls*Bz rows at once)
    k_gemm_mma<<<dim3((Ls * Bz) / 128, Hd / 128), 256>>>(ENC2, W32, nullptr, ENC_W3, Hd);

    // decoder scan: store h_t and (h_t @ w4^T) per step; epilogues batched after
    const float*         hp  = ENC_OUT + (size_t)(Ls - 1) * Bz * Hd;
    const __nv_bfloat16* hp2 = ENC2    + (size_t)(Ls - 1) * Bz * K2;
    for (int t = 0; t < Ls; t++) {
        float* ht = H_ALL + (size_t)t * Bz * Hd;
        k_gemm_mma<<<dim3(Bz / 128, Gd / 128), 256>>>(hp2, WHHD2, dec_bhh, HG, Gd);
        k_gate<<<(Bz * Hd) / 256, 256>>>(XG_DEC, HG, dec_bhh, hp, ht, H2);
        k_gemm_mma<<<dim3(Bz / 128, Hd / 128), 256>>>(H2, W42, nullptr,
                                                      A_ALL + (size_t)t * Bz * Hd, Hd);
        hp = ht; hp2 = H2;
    }

    // batched epilogues
    k_seq_all<<<Bz, 256>>>(ENC_W3, A_ALL, v2, out_seq);
    k_ori_all<<<(Bz * Ls) / 8, 256>>>(H_ALL, wori, bori, out_ori);
}

// round 6
// speedup vs baseline: 2.5521x; 1.5204x over previous
#include <cuda_runtime.h>
#include <cuda_fp16.h>
#include <cstdint>
#include <math.h>

static constexpr int Bz  = 4096;
static constexpr int Ls  = 10;
static constexpr int IND = 8;
static constexpr int Hd  = 512;
static constexpr int Gd  = 1536;   // 3*Hd
static constexpr int KW  = 1024;   // weight split row: [hi 512 | lo 512] fp16

// ---------------- scratch (offsets in float units) ----------------
static constexpr size_t OFF_HG      = 0;                                     // Bz*Gd f32
static constexpr size_t OFF_XG_DEC  = OFF_HG      + (size_t)Bz*Gd;           // Bz*Gd f32
static constexpr size_t OFF_ENC_OUT = OFF_XG_DEC  + (size_t)Bz*Gd;           // Ls*Bz*Hd f32
static constexpr size_t OFF_ENC1    = OFF_ENC_OUT + (size_t)Ls*Bz*Hd;        // Ls*Bz*512 fp16
static constexpr size_t OFF_ENC_W3  = OFF_ENC1    + (size_t)Ls*Bz*Hd/2;      // Ls*Bz*Hd f32
static constexpr size_t OFF_H_ALL   = OFF_ENC_W3  + (size_t)Ls*Bz*Hd;        // Ls*Bz*Hd f32
static constexpr size_t OFF_A_ALL   = OFF_H_ALL   + (size_t)Ls*Bz*Hd;        // Ls*Bz*Hd f32
static constexpr size_t OFF_H1      = OFF_A_ALL   + (size_t)Ls*Bz*Hd;        // Bz*512 fp16
static constexpr size_t OFF_DEC1    = OFF_H1      + (size_t)Bz*Hd/2;         // Bz*512 fp16
static constexpr size_t OFF_WHHE2   = OFF_DEC1    + (size_t)Bz*Hd/2;         // Gd*KW fp16
static constexpr size_t OFF_WHHD2   = OFF_WHHE2   + (size_t)Gd*KW/2;
static constexpr size_t OFF_WIHD2   = OFF_WHHD2   + (size_t)Gd*KW/2;
static constexpr size_t OFF_W32     = OFF_WIHD2   + (size_t)Gd*KW/2;         // Hd*KW fp16
static constexpr size_t OFF_W42     = OFF_W32     + (size_t)Hd*KW/2;
static constexpr size_t OFF_CW      = OFF_W42     + (size_t)Hd*KW/2;         // Gd*IND f32
static constexpr size_t OFF_CB      = OFF_CW      + (size_t)Gd*IND;          // Gd f32
static constexpr size_t SCRATCH_TOTAL = OFF_CB + Gd;

__device__ __align__(1024) float g_scratch[SCRATCH_TOTAL];

// ---------------- math helpers ----------------
__device__ __forceinline__ float sigm_f(float x) { return 1.0f / (1.0f + __expf(-x)); }
__device__ __forceinline__ float tanh_f(float x) {
    float ax = fabsf(x);
    float t  = __expf(-2.0f * ax);
    float r  = __fdividef(1.0f - t, 1.0f + t);
    return copysignf(r, x);
}

// ---------------- PTX helpers ----------------
__device__ __forceinline__ uint32_t smem_u32(const void* p) {
    uint32_t a;
    asm("{ .reg .u64 t; cvta.to.shared.u64 t, %1; cvt.u32.u64 %0, t; }" : "=r"(a) : "l"(p));
    return a;
}
__device__ __forceinline__ void cp16(uint32_t s, const void* g) {
    asm volatile("cp.async.cg.shared.global [%0], [%1], 16;" :: "r"(s), "l"(g) : "memory");
}
__device__ __forceinline__ void ldm_x4(uint32_t& r0, uint32_t& r1, uint32_t& r2, uint32_t& r3,
                                       uint32_t addr) {
    asm volatile("ldmatrix.sync.aligned.m8n8.x4.shared.b16 {%0,%1,%2,%3}, [%4];"
                 : "=r"(r0), "=r"(r1), "=r"(r2), "=r"(r3) : "r"(addr));
}
__device__ __forceinline__ void mma16816(float* c, const uint32_t* a, uint32_t b0, uint32_t b1) {
    asm volatile("mma.sync.aligned.m16n8k16.row.col.f32.f16.f16.f32 "
                 "{%0,%1,%2,%3}, {%4,%5,%6,%7}, {%8,%9}, {%0,%1,%2,%3};"
                 : "+f"(c[0]), "+f"(c[1]), "+f"(c[2]), "+f"(c[3])
                 : "r"(a[0]), "r"(a[1]), "r"(a[2]), "r"(a[3]), "r"(b0), "r"(b1));
}

// ---------------- fp16x2 tensor-core GEMM: C[M,N] = A @ (Whi+Wlo)^T (+bias) ----------------
// A1[M,512] fp16 activations; W2[N,KW] fp16 split rows [hi|lo].
// 16 physical K-tiles of 32; each tile: one A tile vs two B tiles (hi, lo).
// 128x128 CTA tile, 256 threads (8 warps of 32x64), 2-stage cp.async double buffer.
// 80-byte smem rows: bank rotation 20r mod 32 -> conflict-free ldmatrix.
static constexpr int AB_STRIDE = 10240;   // 128 rows * 80 B
static constexpr int BB_STRIDE = 20480;   // 256 rows * 80 B

__global__ void __launch_bounds__(256, 2) k_gemm_mma(
    const __half* __restrict__ A1, const __half* __restrict__ W2,
    const float* __restrict__ bias, float* __restrict__ C, int N)
{
    __shared__ __half As[2][128][40];
    __shared__ __half Bs[2][256][40];
    const int tid  = threadIdx.x;
    const int wid  = tid >> 5, lane = tid & 31;
    const int wm   = wid & 3;          // M-warp: rows wm*32
    const int wn   = wid >> 2;         // N-warp: cols wn*64
    const size_t bm = (size_t)blockIdx.x * 128;
    const size_t bn = (size_t)blockIdx.y * 128;

    const uint32_t sA = smem_u32(As);
    const uint32_t sB = smem_u32(Bs);

    float acc[2][8][4];
#pragma unroll
    for (int i = 0; i < 2; i++)
#pragma unroll
        for (int j = 0; j < 8; j++)
#pragma unroll
            for (int q = 0; q < 4; q++) acc[i][j][q] = 0.0f;

    const int lrow = tid >> 2;             // 0..63
    const int lcol = (tid & 3) << 4;       // byte 0,16,32,48
    const char* aG = (const char*)A1 + (bm + lrow) * 1024 + lcol;   // A row = 512 fp16 = 1024 B
    const char* bG = (const char*)W2 + (bn + lrow) * 2048 + lcol;   // W row = 1024 fp16 = 2048 B
    const uint32_t dA = sA + lrow * 80 + lcol;
    const uint32_t dB = sB + lrow * 80 + lcol;

#define LOAD_TILE(kt, buf)                                                     \
    {                                                                          \
        int ko_ = (kt) * 64;                                                   \
        cp16(dA + (buf) * AB_STRIDE,            aG + ko_);                     \
        cp16(dA + (buf) * AB_STRIDE + 64 * 80,  aG + 64 * 1024 + ko_);         \
        cp16(dB + (buf) * BB_STRIDE,            bG + ko_);                     \
        cp16(dB + (buf) * BB_STRIDE + 64 * 80,  bG + 64 * 2048 + ko_);         \
        cp16(dB + (buf) * BB_STRIDE + 128 * 80, bG + 1024 + ko_);              \
        cp16(dB + (buf) * BB_STRIDE + 192 * 80, bG + 64 * 2048 + 1024 + ko_);  \
        asm volatile("cp.async.commit_group;" ::: "memory");                   \
    }

    LOAD_TILE(0, 0);

    const uint32_t mA0 = sA + (wm * 32 + (lane & 15)) * 80 + ((lane >> 4) << 4);
    const uint32_t mB0 = sB + (wn * 64 + (lane & 15)) * 80 + ((lane >> 4) << 4);

    for (int kt = 0; kt < 16; kt++) {
        int buf = kt & 1;
        if (kt < 15) {
            LOAD_TILE(kt + 1, buf ^ 1);
            asm volatile("cp.async.wait_group 1;" ::: "memory");
        } else {
            asm volatile("cp.async.wait_group 0;" ::: "memory");
        }
        __syncthreads();

#pragma unroll
        for (int ks = 0; ks < 2; ks++) {
            uint32_t a[2][4], b[4][4];
#pragma unroll
            for (int mf = 0; mf < 2; mf++)
                ldm_x4(a[mf][0], a[mf][1], a[mf][2], a[mf][3],
                       mA0 + buf * AB_STRIDE + mf * 16 * 80 + ks * 32);
            // hi plane
#pragma unroll
            for (int nb = 0; nb < 4; nb++)
                ldm_x4(b[nb][0], b[nb][1], b[nb][2], b[nb][3],
                       mB0 + buf * BB_STRIDE + nb * 16 * 80 + ks * 32);
#pragma unroll
            for (int mf = 0; mf < 2; mf++)
#pragma unroll
                for (int nb = 0; nb < 4; nb++) {
                    mma16816(acc[mf][2 * nb + 0], a[mf], b[nb][0], b[nb][2]);
                    mma16816(acc[mf][2 * nb + 1], a[mf], b[nb][1], b[nb][3]);
                }
            // lo plane
#pragma unroll
            for (int nb = 0; nb < 4; nb++)
                ldm_x4(b[nb][0], b[nb][1], b[nb][2], b[nb][3],
                       mB0 + buf * BB_STRIDE + 128 * 80 + nb * 16 * 80 + ks * 32);
#pragma unroll
            for (int mf = 0; mf < 2; mf++)
#pragma unroll
                for (int nb = 0; nb < 4; nb++) {
                    mma16816(acc[mf][2 * nb + 0], a[mf], b[nb][0], b[nb][2]);
                    mma16816(acc[mf][2 * nb + 1], a[mf], b[nb][1], b[nb][3]);
                }
        }
        __syncthreads();
    }
#undef LOAD_TILE

    // epilogue
#pragma unroll
    for (int mf = 0; mf < 2; mf++) {
#pragma unroll
        for (int nf = 0; nf < 8; nf++) {
            size_t r0 = bm + wm * 32 + mf * 16 + (lane >> 2);
            int    c0 = (int)bn + wn * 64 + nf * 8 + (lane & 3) * 2;
            float bv0 = 0.f, bv1 = 0.f;
            if (bias) { bv0 = bias[c0]; bv1 = bias[c0 + 1]; }
            float2 o0 = make_float2(acc[mf][nf][0] + bv0, acc[mf][nf][1] + bv1);
            float2 o1 = make_float2(acc[mf][nf][2] + bv0, acc[mf][nf][3] + bv1);
            *reinterpret_cast<float2*>(&C[r0 * (size_t)N + c0])       = o0;
            *reinterpret_cast<float2*>(&C[(r0 + 8) * (size_t)N + c0]) = o1;
        }
    }
}

// ---------------- weight split: f32[n,512] -> fp16[n,1024] hi|lo ----------------
__global__ void k_split_w(const float* __restrict__ in, __half* __restrict__ out)
{
    size_t idx = (size_t)blockIdx.x * blockDim.x + threadIdx.x;
    size_t r = idx >> 9; int j = (int)(idx & 511);
    float v = in[idx];
    __half hi = __float2half(v);
    float lo = v - __half2float(hi);
    out[r * KW + j]       = hi;
    out[r * KW + 512 + j] = __float2half(lo);
}

// ---------------- cast: f32 -> fp16 ----------------
__global__ void k_cast(const float* __restrict__ in, __half* __restrict__ out)
{
    size_t idx = (size_t)blockIdx.x * blockDim.x + threadIdx.x;
    out[idx] = __float2half(in[idx]);
}

// ---------------- combine: cw = enc_wih @ emb_w, cb = enc_wih@emb_b + enc_bih ----------------
__global__ void k_combine(const float* __restrict__ enc_wih, const float* __restrict__ emb_w,
                          const float* __restrict__ emb_b,  const float* __restrict__ enc_bih,
                          float* __restrict__ cw, float* __restrict__ cb)
{
    int g = blockIdx.x, tid = threadIdx.x;
    float p[IND + 1];
#pragma unroll
    for (int i = 0; i <= IND; i++) p[i] = 0.0f;
    const float* wr = enc_wih + (size_t)g * Hd;
    for (int k = tid; k < Hd; k += 128) {
        float wv = wr[k];
#pragma unroll
        for (int i = 0; i < IND; i++) p[i] += wv * emb_w[(size_t)k * IND + i];
        p[IND] += wv * emb_b[k];
    }
#pragma unroll
    for (int i = 0; i <= IND; i++)
        for (int o = 16; o; o >>= 1) p[i] += __shfl_xor_sync(0xffffffffu, p[i], o);
    __shared__ float red[IND + 1][4];
    int wid = tid >> 5, lane = tid & 31;
    if (!lane)
#pragma unroll
        for (int i = 0; i <= IND; i++) red[i][wid] = p[i];
    __syncthreads();
    if (tid <= IND) {
        float s = red[tid][0] + red[tid][1] + red[tid][2] + red[tid][3];
        if (tid < IND) cw[(size_t)g * IND + tid] = s;
        else           cb[g] = s + enc_bih[g];
    }
}

// ---------------- encoder GRU gate with inline input-gate dot ----------------
__global__ void k_gate_enc(const float* __restrict__ items, int t,
                           const float* __restrict__ cw, const float* __restrict__ cb,
                           const float* __restrict__ hg, const float* __restrict__ bhh,
                           const float* __restrict__ hprev,
                           float* __restrict__ hout, __half* __restrict__ h1)
{
    int idx = blockIdx.x * blockDim.x + threadIdx.x;
    int b = idx >> 9, j = idx & 511;
    const float4* it = reinterpret_cast<const float4*>(items + ((size_t)b * Ls + t) * IND);
    float4 i0 = it[0], i1 = it[1];

    auto xdot = [&](int g) {
        const float4* w = reinterpret_cast<const float4*>(cw + (size_t)g * IND);
        float4 w0 = w[0], w1 = w[1];
        float acc = cb[g];
        acc += i0.x * w0.x + i0.y * w0.y + i0.z * w0.z + i0.w * w0.w;
        acc += i1.x * w1.x + i1.y * w1.y + i1.z * w1.z + i1.w * w1.w;
        return acc;
    };
    float xr = xdot(j), xz = xdot(Hd + j), xn = xdot(2 * Hd + j);

    float hr, hz, hn;
    if (hg) {
        const float* hrow = hg + (size_t)b * Gd;
        hr = hrow[j]; hz = hrow[Hd + j]; hn = hrow[2 * Hd + j];
    } else {
        hr = bhh[j]; hz = bhh[Hd + j]; hn = bhh[2 * Hd + j];
    }
    float hp = hprev ? hprev[idx] : 0.0f;
    float r = sigm_f(xr + hr);
    float z = sigm_f(xz + hz);
    float n = tanh_f(xn + r * hn);
    float v = n + z * (hp - n);
    hout[idx] = v;
    h1[idx] = __float2half(v);
}

// ---------------- decoder GRU gate ----------------
__global__ void k_gate_dec(const float* __restrict__ xg, const float* __restrict__ hg,
                           const float* __restrict__ hprev,
                           float* __restrict__ hout, __half* __restrict__ h1)
{
    int idx = blockIdx.x * blockDim.x + threadIdx.x;
    int b = idx >> 9, j = idx & 511;
    const float* xrow = xg + (size_t)b * Gd;
    const float* hrow = hg + (size_t)b * Gd;
    float r = sigm_f(xrow[j] + hrow[j]);
    float z = sigm_f(xrow[Hd + j] + hrow[Hd + j]);
    float n = tanh_f(xrow[2 * Hd + j] + r * hrow[2 * Hd + j]);
    float hp = hprev[idx];
    float v = n + z * (hp - n);
    hout[idx] = v;
    h1[idx] = __float2half(v);
}

// ---------------- batched out_seq over all (t, l): one block per b ----------------
__global__ void __launch_bounds__(256) k_seq_all(
    const float* __restrict__ encw3, const float* __restrict__ A_all,
    const float* __restrict__ v2, float* __restrict__ out)
{
    int b = blockIdx.x, tid = threadIdx.x;
    int wid = tid >> 5, lane = tid & 31;
    __shared__ float Ash[Ls][Hd];
    __shared__ float v2s[Hd];
    __shared__ float red[8][Ls];
    for (int i = tid; i < Hd; i += 256) v2s[i] = v2[i];
    for (int t = 0; t < Ls; t++)
        for (int i = tid; i < Hd; i += 256)
            Ash[t][i] = A_all[((size_t)t * Bz + b) * Hd + i];
    __syncthreads();

    for (int l = 0; l < Ls; l++) {
        const float* e = encw3 + ((size_t)l * Bz + b) * Hd;
        float s[Ls];
#pragma unroll
        for (int t = 0; t < Ls; t++) s[t] = 0.0f;
#pragma unroll
        for (int it = 0; it < 2; it++) {
            int k = tid + it * 256;
            float ek = e[k], vk = v2s[k];
#pragma unroll
            for (int t = 0; t < Ls; t++) s[t] += vk * tanh_f(ek + Ash[t][k]);
        }
#pragma unroll
        for (int t = 0; t < Ls; t++)
            for (int o = 16; o; o >>= 1) s[t] += __shfl_xor_sync(0xffffffffu, s[t], o);
        if (!lane)
#pragma unroll
            for (int t = 0; t < Ls; t++) red[wid][t] = s[t];
        __syncthreads();
        if (tid < Ls) {
            float tot = 0.0f;
#pragma unroll
            for (int w = 0; w < 8; w++) tot += red[w][tid];
            out[((size_t)b * Ls + tid) * Ls + l] = tot;
        }
        __syncthreads();
    }
}

// ---------------- batched out_ori: one warp per (t, b) ----------------
__global__ void k_ori_all(const float* __restrict__ H_all, const float* __restrict__ wori,
                          const float* __restrict__ bori, float* __restrict__ out)
{
    int gw   = (blockIdx.x * blockDim.x + threadIdx.x) >> 5;  // t*Bz + b
    int lane = threadIdx.x & 31;
    int t = gw >> 12, b = gw & 4095;
    float s[6] = {0, 0, 0, 0, 0, 0};
    const float* hb = H_all + ((size_t)t * Bz + b) * Hd;
    for (int k = lane; k < Hd; k += 32) {
        float hv = hb[k];
#pragma unroll
        for (int j = 0; j < 6; j++) s[j] += hv * wori[(size_t)j * Gd + Hd + k];
    }
#pragma unroll
    for (int j = 0; j < 6; j++)
        for (int o = 16; o; o >>= 1) s[j] += __shfl_xor_sync(0xffffffffu, s[j], o);
    if (!lane)
#pragma unroll
        for (int j = 0; j < 6; j++)
            out[((size_t)b * Ls + t) * 6 + j] = s[j] + bori[j];
}

// ---------------- launch ----------------
extern "C" void kernel_launch(void* const* d_in, const int* in_sizes, int n_in,
                              void* d_out, int out_size)
{
    const float* items    = (const float*)d_in[0];
    const float* dec_in   = (const float*)d_in[1];
    const float* emb_w    = (const float*)d_in[2];
    const float* emb_b    = (const float*)d_in[3];
    const float* enc_wih  = (const float*)d_in[4];
    const float* enc_whh  = (const float*)d_in[5];
    const float* enc_bih  = (const float*)d_in[6];
    const float* enc_bhh  = (const float*)d_in[7];
    const float* dec_wih  = (const float*)d_in[8];
    const float* dec_whh  = (const float*)d_in[9];
    const float* dec_bih  = (const float*)d_in[10];
    const float* dec_bhh  = (const float*)d_in[11];
    const float* w3       = (const float*)d_in[14];
    const float* w4       = (const float*)d_in[15];
    const float* v2       = (const float*)d_in[20];
    const float* wori     = (const float*)d_in[23];
    const float* bori     = (const float*)d_in[24];

    float* out_seq = (float*)d_out;                        // (Bz, Ls, Ls)
    float* out_ori = (float*)d_out + (size_t)Bz * Ls * Ls; // (Bz, Ls, 6)

    float* S = nullptr;
    cudaGetSymbolAddress((void**)&S, g_scratch);
    float* HG      = S + OFF_HG;
    float* XG_DEC  = S + OFF_XG_DEC;
    float* ENC_OUT = S + OFF_ENC_OUT;
    float* ENC_W3  = S + OFF_ENC_W3;
    float* H_ALL   = S + OFF_H_ALL;
    float* A_ALL   = S + OFF_A_ALL;
    float* CW      = S + OFF_CW;
    float* CB      = S + OFF_CB;
    __half* ENC1  = (__half*)(S + OFF_ENC1);
    __half* H1    = (__half*)(S + OFF_H1);
    __half* DEC1  = (__half*)(S + OFF_DEC1);
    __half* WHHE2 = (__half*)(S + OFF_WHHE2);
    __half* WHHD2 = (__half*)(S + OFF_WHHD2);
    __half* WIHD2 = (__half*)(S + OFF_WIHD2);
    __half* W32   = (__half*)(S + OFF_W32);
    __half* W42   = (__half*)(S + OFF_W42);

    // weight splits + decoder-input cast
    k_split_w<<<(Gd * Hd) / 256, 256>>>(enc_whh, WHHE2);
    k_split_w<<<(Gd * Hd) / 256, 256>>>(dec_whh, WHHD2);
    k_split_w<<<(Gd * Hd) / 256, 256>>>(dec_wih, WIHD2);
    k_split_w<<<(Hd * Hd) / 256, 256>>>(w3, W32);
    k_split_w<<<(Hd * Hd) / 256, 256>>>(w4, W42);
    k_cast<<<(Bz * Hd) / 256, 256>>>(dec_in, DEC1);

    // combined encoder input weights
    k_combine<<<Gd, 128>>>(enc_wih, emb_w, emb_b, enc_bih, CW, CB);

    // decoder input gates (step-invariant)
    k_gemm_mma<<<dim3(Bz / 128, Gd / 128), 256>>>(DEC1, WIHD2, dec_bih, XG_DEC, Gd);

    // encoder GRU scan (input gates computed inline)
    for (int t = 0; t < Ls; t++) {
        const float* hp = t ? (ENC_OUT + (size_t)(t - 1) * Bz * Hd) : nullptr;
        if (t)
            k_gemm_mma<<<dim3(Bz / 128, Gd / 128), 256>>>(
                ENC1 + (size_t)(t - 1) * Bz * Hd, WHHE2, enc_bhh, HG, Gd);
        k_gate_enc<<<(Bz * Hd) / 256, 256>>>(items, t, CW, CB,
                                             t ? HG : nullptr, enc_bhh, hp,
                                             ENC_OUT + (size_t)t * Bz * Hd,
                                             ENC1 + (size_t)t * Bz * Hd);
    }

    // enc_w3 = enc_out @ w3^T  (all Ls*Bz rows at once)
    k_gemm_mma<<<dim3((Ls * Bz) / 128, Hd / 128), 256>>>(ENC1, W32, nullptr, ENC_W3, Hd);

    // decoder scan
    const float*  hp  = ENC_OUT + (size_t)(Ls - 1) * Bz * Hd;
    const __half* hp1 = ENC1    + (size_t)(Ls - 1) * Bz * Hd;
    for (int t = 0; t < Ls; t++) {
        float* ht = H_ALL + (size_t)t * Bz * Hd;
        k_gemm_mma<<<dim3(Bz / 128, Gd / 128), 256>>>(hp1, WHHD2, dec_bhh, HG, Gd);
        k_gate_dec<<<(Bz * Hd) / 256, 256>>>(XG_DEC, HG, hp, ht, H1);
        k_gemm_mma<<<dim3(Bz / 128, Hd / 128), 256>>>(H1, W42, nullptr,
                                                      A_ALL + (size_t)t * Bz * Hd, Hd);
        hp = ht; hp1 = H1;
    }

    // batched epilogues
    k_seq_all<<<Bz, 256>>>(ENC_W3, A_ALL, v2, out_seq);
    k_ori_all<<<(Bz * Ls) / 8, 256>>>(H_ALL, wori, bori, out_ori);
}